// round 7
// baseline (speedup 1.0000x reference)
#include <cuda_runtime.h>

#define NB 8
#define OP 400
#define MA 200
#define F 64

// Scratch (allocation-free rule: __device__ globals)
__device__ float g_hop[NB*OP*F];   // h_op = x @ W_op
__device__ float g_sop[NB*OP];     // h_op . a_op
__device__ float g_h  [NB*MA*F];   // h = y @ W_ma
__device__ float g_sma[NB*MA];     // h . a_ma
__device__ float g_vedge[F];       // W_edge @ a_edge

__device__ __forceinline__ float warp_sum(float v) {
    v += __shfl_xor_sync(0xffffffffu, v, 16);
    v += __shfl_xor_sync(0xffffffffu, v, 8);
    v += __shfl_xor_sync(0xffffffffu, v, 4);
    v += __shfl_xor_sync(0xffffffffu, v, 2);
    v += __shfl_xor_sync(0xffffffffu, v, 1);
    return v;
}

// ---------------------------------------------------------------------------
// Prep kernel: small GEMVs.
// ---------------------------------------------------------------------------
__global__ void prep_kernel(const float* __restrict__ x, const float* __restrict__ y,
                            const float* __restrict__ Wop, const float* __restrict__ Wma,
                            const float* __restrict__ Wedge, const float* __restrict__ att)
{
    int blk = blockIdx.x;
    int t = threadIdx.x;

    if (blk == NB*OP + NB*MA) {
        float acc = 0.f;
        #pragma unroll
        for (int f = 0; f < F; f++) acc += Wedge[t*F + f] * att[2*F + f];
        g_vedge[t] = acc;
        return;
    }

    const float* in; const float* W; const float* a;
    float* hout; float* sout;
    if (blk < NB*OP) {
        int row = blk;
        in = x + row*F; W = Wop; a = att;
        hout = g_hop + row*F; sout = g_sop + row;
    } else {
        int row = blk - NB*OP;
        in = y + row*F; W = Wma; a = att + F;
        hout = g_h + row*F; sout = g_sma + row;
    }

    __shared__ float srow[F];
    __shared__ float sred[2];
    srow[t] = in[t];
    __syncthreads();

    float acc = 0.f;
    #pragma unroll
    for (int i = 0; i < F; i++) acc += srow[i] * W[i*F + t];
    hout[t] = acc;

    float v = warp_sum(acc * a[t]);
    if ((t & 31) == 0) sred[t >> 5] = v;
    __syncthreads();
    if (t == 0) sout[0] = sred[0] + sred[1];
}

// ---------------------------------------------------------------------------
// Main kernel: one CTA per (b, m). Masked n's compacted into smem. Each warp
// processes 16-n blocks:
//   phase 1: 16 coalesced z-row loads (float2/lane), per-lane partial dots
//            into registers (no shuffles, 16-deep MLP)
//   transpose partials through smem (pad-33, conflict-free), one shfl(16)
//   e/leakyrelu/exp computed 16-wide (lane-per-n), p parked in smem
//   accumulate: re-read z (L2-hot) + hop, 4 FMA per n, unroll-4
// Softmax without max-subtraction (|e| small by construction).
// ---------------------------------------------------------------------------
__global__ __launch_bounds__(128) void edge_gat_kernel(
    const float*  __restrict__ z,
    const int*    __restrict__ adj,
    const float*  __restrict__ Wedge,
    float*        __restrict__ out)
{
    const int bid = blockIdx.x;
    const int b = bid / MA;
    const int m = bid % MA;
    const int tid = threadIdx.x;
    const int w = tid >> 5;
    const int lane = tid & 31;
    const int l0 = lane & 15;      // n-slot within block
    const int hh = lane >> 4;      // which half of the 32 partial columns

    __shared__ int   s_cnt;
    __shared__ int   s_idx[OP];     // compacted masked n
    __shared__ float s_sopc[OP];    // compacted sop values
    __shared__ float s_part[4][16][33];
    __shared__ float s_p[4][16];
    __shared__ float s_pz[4*F];
    __shared__ float s_ph[4*F];
    __shared__ float s_pd[4];
    __shared__ float s_accz[F];

    if (tid == 0) s_cnt = 0;
    __syncthreads();

    // ballot-compaction (warp-uniform trip count: 512 = 4 iters for everyone)
    for (int i = tid; i < 512; i += 128) {
        int mk = 0;
        float sop = 0.f;
        if (i < OP) {
            mk = adj[(b*OP + i)*MA + m];     // adjT[b,m,i]
            if (mk) sop = g_sop[b*OP + i];
        }
        unsigned ball = __ballot_sync(0xffffffffu, mk != 0);
        int base = 0;
        if (lane == 0 && ball) base = atomicAdd(&s_cnt, __popc(ball));
        base = __shfl_sync(0xffffffffu, base, 0);
        if (mk) {
            int off = base + __popc(ball & ((1u << lane) - 1u));
            s_idx[off]  = i;
            s_sopc[off] = sop;
        }
    }
    const float  sma = g_sma[b*MA + m];
    const float2 ve  = ((const float2*)g_vedge)[lane];
    __syncthreads();
    const int cnt = s_cnt;

    float2 accz = make_float2(0.f, 0.f);
    float2 acch = make_float2(0.f, 0.f);
    float  denom = 0.f;

    const float2* zb = (const float2*)z;
    const float2* hb = (const float2*)g_hop;

    // warp w handles n-blocks [w*16 + 64k, +16)
    #pragma unroll 1
    for (int base = w * 16; base < cnt; base += 64) {
        const int nv = min(16, cnt - base);

        // --- phase 1: coalesced loads, per-lane partial dots ---
        float part[16];
        #pragma unroll
        for (int u = 0; u < 16; u++) {
            part[u] = 0.f;
            if (u < nv) {
                int n = s_idx[base + u];
                float2 zv = zb[((b*OP + n)*MA + m)*32 + lane];
                part[u] = zv.x*ve.x + zv.y*ve.y;
            }
        }

        // --- transpose partials through smem ---
        #pragma unroll
        for (int u = 0; u < 16; u++) s_part[w][u][lane] = part[u];
        __syncwarp();

        float dot = 0.f;
        #pragma unroll
        for (int j = 0; j < 16; j++) dot += s_part[w][l0][hh*16 + j];
        dot += __shfl_xor_sync(0xffffffffu, dot, 16);

        // --- e / leaky / exp (lane-per-n, 16-wide) ---
        const int jn = base + l0;
        const bool val = jn < cnt;
        float e = dot + (val ? s_sopc[jn] : 0.f) + sma;
        e = fmaxf(e, 0.01f*e);                 // leaky_relu(0.01)
        float p = val ? __expf(e) : 0.f;       // no max-sub: |e| small
        if (hh == 0) { s_p[w][l0] = p; denom += p; }
        __syncwarp();

        // --- accumulate: re-read z (L2-hot) + hop ---
        #pragma unroll 4
        for (int u = 0; u < 16; u++) {
            if (u < nv) {
                float pu = s_p[w][u];
                int n = s_idx[base + u];
                float2 zv = zb[((b*OP + n)*MA + m)*32 + lane];
                float2 hv = hb[(b*OP + n)*32 + lane];
                accz.x += pu*zv.x; accz.y += pu*zv.y;
                acch.x += pu*hv.x; acch.y += pu*hv.y;
            }
        }
        __syncwarp();   // protect s_part/s_p before next block rewrites them
    }

    // denom: lanes hh==0 each hold partial sums over their l0 slots
    denom = warp_sum(denom);

    s_pz[w*F + 2*lane]   = accz.x;
    s_pz[w*F + 2*lane+1] = accz.y;
    s_ph[w*F + 2*lane]   = acch.x;
    s_ph[w*F + 2*lane+1] = acch.y;
    if (lane == 0) s_pd[w] = denom;
    __syncthreads();

    float ah = 0.f, dn = 0.f;
    if (tid < F) {
        const int f = tid;
        float az = s_pz[f] + s_pz[F+f] + s_pz[2*F+f] + s_pz[3*F+f];
        ah       = s_ph[f] + s_ph[F+f] + s_ph[2*F+f] + s_ph[3*F+f];
        dn       = s_pd[0] + s_pd[1] + s_pd[2] + s_pd[3];
        s_accz[f] = az;
    }
    __syncthreads();

    if (tid < F) {
        const int f = tid;
        float val = ah;
        #pragma unroll
        for (int kk = 0; kk < F; kk++)
            val += s_accz[kk] * Wedge[kk*F + f];
        float hbv = g_h[(b*MA + m)*F + f];
        // row_empty (dn==0): h_prime contribution zeroed -> just h
        float hp = (dn > 0.f) ? (val / dn + hbv) : hbv;
        out[(b*MA + m)*F + f] = (hp > 0.f) ? hp : expm1f(hp);   // ELU
    }
}

extern "C" void kernel_launch(void* const* d_in, const int* in_sizes, int n_in,
                              void* d_out, int out_size)
{
    const float* x    = (const float*)d_in[0];
    const float* y    = (const float*)d_in[1];
    const float* z    = (const float*)d_in[2];
    const int*   adj  = (const int*)  d_in[3];
    const float* Wop  = (const float*)d_in[4];
    const float* Wma  = (const float*)d_in[5];
    const float* We   = (const float*)d_in[6];
    const float* att  = (const float*)d_in[7];
    float* out = (float*)d_out;

    prep_kernel<<<NB*OP + NB*MA + 1, F>>>(x, y, Wop, Wma, We, att);
    edge_gat_kernel<<<NB*MA, 128>>>(z, adj, We, out);
}

// round 8
// speedup vs baseline: 1.2010x; 1.2010x over previous
#include <cuda_runtime.h>

#define NB 8
#define OP 400
#define MA 200
#define F 64

// Scratch (allocation-free rule: __device__ globals)
__device__ float g_hop[NB*OP*F];   // h_op = x @ W_op
__device__ float g_sop[NB*OP];     // h_op . a_op
__device__ float g_h  [NB*MA*F];   // h = y @ W_ma
__device__ float g_sma[NB*MA];     // h . a_ma
__device__ float g_vedge[F];       // W_edge @ a_edge

__device__ __forceinline__ float warp_sum(float v) {
    v += __shfl_xor_sync(0xffffffffu, v, 16);
    v += __shfl_xor_sync(0xffffffffu, v, 8);
    v += __shfl_xor_sync(0xffffffffu, v, 4);
    v += __shfl_xor_sync(0xffffffffu, v, 2);
    v += __shfl_xor_sync(0xffffffffu, v, 1);
    return v;
}

// ---------------------------------------------------------------------------
// Prep kernel: small GEMVs.
// ---------------------------------------------------------------------------
__global__ void prep_kernel(const float* __restrict__ x, const float* __restrict__ y,
                            const float* __restrict__ Wop, const float* __restrict__ Wma,
                            const float* __restrict__ Wedge, const float* __restrict__ att)
{
    int blk = blockIdx.x;
    int t = threadIdx.x;

    if (blk == NB*OP + NB*MA) {
        float acc = 0.f;
        #pragma unroll
        for (int f = 0; f < F; f++) acc += Wedge[t*F + f] * att[2*F + f];
        g_vedge[t] = acc;
        return;
    }

    const float* in; const float* W; const float* a;
    float* hout; float* sout;
    if (blk < NB*OP) {
        int row = blk;
        in = x + row*F; W = Wop; a = att;
        hout = g_hop + row*F; sout = g_sop + row;
    } else {
        int row = blk - NB*OP;
        in = y + row*F; W = Wma; a = att + F;
        hout = g_h + row*F; sout = g_sma + row;
    }

    __shared__ float srow[F];
    __shared__ float sred[2];
    srow[t] = in[t];
    __syncthreads();

    float acc = 0.f;
    #pragma unroll
    for (int i = 0; i < F; i++) acc += srow[i] * W[i*F + t];
    hout[t] = acc;

    float v = warp_sum(acc * a[t]);
    if ((t & 31) == 0) sred[t >> 5] = v;
    __syncthreads();
    if (t == 0) sout[0] = sred[0] + sred[1];
}

// ---------------------------------------------------------------------------
// Main kernel: one CTA per (b, m). Masked n's compacted into smem (R5 proven).
// Half-warp per n with float4: each warp instruction covers TWO n's.
//   - LDG.128 per lane: lanes 0-15 -> n_even, lanes 16-31 -> n_odd
//   - dot reduction: 4-deep butterfly (xor 8,4,2,1), both halves in the same
//     instructions -> 4 shfl+4 add per 2 n's
//   - e/leaky/exp redundant across the 16 lanes of each half (no broadcast)
//   - accumulators float4/lane; halves combined once per warp via shfl(16)
// Softmax without max-subtraction (|e| small by construction).
// ---------------------------------------------------------------------------
__global__ __launch_bounds__(128) void edge_gat_kernel(
    const float*  __restrict__ z,
    const int*    __restrict__ adj,
    const float*  __restrict__ Wedge,
    float*        __restrict__ out)
{
    const int bid = blockIdx.x;
    const int b = bid / MA;
    const int m = bid % MA;
    const int tid = threadIdx.x;
    const int w = tid >> 5;
    const int lane = tid & 31;
    const int l4 = lane & 15;      // float4 slot within half (f = 4*l4..4*l4+3)
    const int hh = lane >> 4;      // half id: 0 -> even n of unit, 1 -> odd

    __shared__ int   s_cnt;
    __shared__ int   s_idx[OP];     // compacted masked n
    __shared__ float s_sopc[OP];    // compacted sop values
    __shared__ float4 s_pz4[4*16];
    __shared__ float4 s_ph4[4*16];
    __shared__ float s_pd[4];
    __shared__ float s_accz[F];

    if (tid == 0) s_cnt = 0;
    __syncthreads();

    // ballot-compaction (warp-uniform trip count: 512 = 4 iters for everyone)
    for (int i = tid; i < 512; i += 128) {
        int mk = 0;
        float sop = 0.f;
        if (i < OP) {
            mk = adj[(b*OP + i)*MA + m];     // adjT[b,m,i]
            if (mk) sop = g_sop[b*OP + i];
        }
        unsigned ball = __ballot_sync(0xffffffffu, mk != 0);
        int base = 0;
        if (lane == 0 && ball) base = atomicAdd(&s_cnt, __popc(ball));
        base = __shfl_sync(0xffffffffu, base, 0);
        if (mk) {
            int off = base + __popc(ball & ((1u << lane) - 1u));
            s_idx[off]  = i;
            s_sopc[off] = sop;
        }
    }
    const float  sma = g_sma[b*MA + m];
    const float4 ve  = ((const float4*)g_vedge)[l4];
    __syncthreads();
    const int cnt = s_cnt;
    const int U = (cnt + 1) >> 1;    // units of 2 n's

    float4 accz = make_float4(0.f, 0.f, 0.f, 0.f);
    float4 acch = make_float4(0.f, 0.f, 0.f, 0.f);
    float  denom = 0.f;   // per-half replicated; halves disjoint

    const float4* zb4 = (const float4*)z;
    const float4* hb4 = (const float4*)g_hop;

    // warp w handles units u = w + 4k, unrolled x2 (4 n in flight)
    #pragma unroll 1
    for (int u0 = w; u0 < U; u0 += 8) {
        bool  ok[2]; float sop[2];
        float4 zv[2], hv[2];
        #pragma unroll
        for (int t = 0; t < 2; t++) {
            int u  = u0 + 4*t;
            int jn = 2*u + hh;
            ok[t] = (u < U) && (jn < cnt);
            int jc = ok[t] ? jn : 0;
            int n  = s_idx[jc];
            sop[t] = s_sopc[jc];
            if (ok[t]) {
                zv[t] = zb4[((b*OP + n)*MA + m)*16 + l4];
                hv[t] = hb4[(b*OP + n)*16 + l4];
            } else {
                zv[t] = make_float4(0.f,0.f,0.f,0.f);
                hv[t] = make_float4(0.f,0.f,0.f,0.f);
            }
        }
        float d[2];
        #pragma unroll
        for (int t = 0; t < 2; t++)
            d[t] = zv[t].x*ve.x + zv[t].y*ve.y + zv[t].z*ve.z + zv[t].w*ve.w;
        // 4-deep butterfly within each 16-lane half; both units interleaved
        #pragma unroll
        for (int o = 8; o; o >>= 1) {
            #pragma unroll
            for (int t = 0; t < 2; t++)
                d[t] += __shfl_xor_sync(0xffffffffu, d[t], o);
        }
        #pragma unroll
        for (int t = 0; t < 2; t++) {
            float e = d[t] + sop[t] + sma;
            e = fmaxf(e, 0.01f*e);                   // leaky_relu(0.01)
            float p = ok[t] ? __expf(e) : 0.f;       // no max-sub: |e| small
            denom += p;
            accz.x += p*zv[t].x; accz.y += p*zv[t].y;
            accz.z += p*zv[t].z; accz.w += p*zv[t].w;
            acch.x += p*hv[t].x; acch.y += p*hv[t].y;
            acch.z += p*hv[t].z; acch.w += p*hv[t].w;
        }
    }

    // combine halves (disjoint n-sets, same f-layout)
    accz.x += __shfl_xor_sync(0xffffffffu, accz.x, 16);
    accz.y += __shfl_xor_sync(0xffffffffu, accz.y, 16);
    accz.z += __shfl_xor_sync(0xffffffffu, accz.z, 16);
    accz.w += __shfl_xor_sync(0xffffffffu, accz.w, 16);
    acch.x += __shfl_xor_sync(0xffffffffu, acch.x, 16);
    acch.y += __shfl_xor_sync(0xffffffffu, acch.y, 16);
    acch.z += __shfl_xor_sync(0xffffffffu, acch.z, 16);
    acch.w += __shfl_xor_sync(0xffffffffu, acch.w, 16);
    denom  += __shfl_xor_sync(0xffffffffu, denom, 16);

    if (lane < 16) {
        s_pz4[w*16 + l4] = accz;
        s_ph4[w*16 + l4] = acch;
        if (lane == 0) s_pd[w] = denom;
    }
    __syncthreads();

    float ah = 0.f, dn = 0.f;
    if (tid < F) {
        const int f = tid;
        const float* pz = (const float*)s_pz4;
        const float* ph = (const float*)s_ph4;
        float az = pz[f] + pz[F+f] + pz[2*F+f] + pz[3*F+f];
        ah       = ph[f] + ph[F+f] + ph[2*F+f] + ph[3*F+f];
        dn       = s_pd[0] + s_pd[1] + s_pd[2] + s_pd[3];
        s_accz[f] = az;
    }
    __syncthreads();

    if (tid < F) {
        const int f = tid;
        float val = ah;
        #pragma unroll
        for (int kk = 0; kk < F; kk++)
            val += s_accz[kk] * Wedge[kk*F + f];
        float hbv = g_h[(b*MA + m)*F + f];
        // row_empty (dn==0): h_prime contribution zeroed -> just h
        float hp = (dn > 0.f) ? (val / dn + hbv) : hbv;
        out[(b*MA + m)*F + f] = (hp > 0.f) ? hp : expm1f(hp);   // ELU
    }
}

extern "C" void kernel_launch(void* const* d_in, const int* in_sizes, int n_in,
                              void* d_out, int out_size)
{
    const float* x    = (const float*)d_in[0];
    const float* y    = (const float*)d_in[1];
    const float* z    = (const float*)d_in[2];
    const int*   adj  = (const int*)  d_in[3];
    const float* Wop  = (const float*)d_in[4];
    const float* Wma  = (const float*)d_in[5];
    const float* We   = (const float*)d_in[6];
    const float* att  = (const float*)d_in[7];
    float* out = (float*)d_out;

    prep_kernel<<<NB*OP + NB*MA + 1, F>>>(x, y, Wop, Wma, We, att);
    edge_gat_kernel<<<NB*MA, 128>>>(z, adj, We, out);
}

// round 10
// speedup vs baseline: 1.2772x; 1.0634x over previous
#include <cuda_runtime.h>

#define NB 8
#define OP 400
#define MA 200
#define F 64

// Scratch (allocation-free rule: __device__ globals)
__device__ float g_hop[NB*OP*F];   // h_op = x @ W_op
__device__ float g_sop[NB*OP];     // h_op . a_op
__device__ float g_h  [NB*MA*F];   // h = y @ W_ma
__device__ float g_sma[NB*MA];     // h . a_ma
__device__ float g_vedge[F];       // W_edge @ a_edge

__device__ __forceinline__ float warp_sum(float v) {
    v += __shfl_xor_sync(0xffffffffu, v, 16);
    v += __shfl_xor_sync(0xffffffffu, v, 8);
    v += __shfl_xor_sync(0xffffffffu, v, 4);
    v += __shfl_xor_sync(0xffffffffu, v, 2);
    v += __shfl_xor_sync(0xffffffffu, v, 1);
    return v;
}

// ---------------------------------------------------------------------------
// Prep kernel: small GEMVs.
// ---------------------------------------------------------------------------
__global__ void prep_kernel(const float* __restrict__ x, const float* __restrict__ y,
                            const float* __restrict__ Wop, const float* __restrict__ Wma,
                            const float* __restrict__ Wedge, const float* __restrict__ att)
{
    int blk = blockIdx.x;
    int t = threadIdx.x;

    if (blk == NB*OP + NB*MA) {
        float acc = 0.f;
        #pragma unroll
        for (int f = 0; f < F; f++) acc += Wedge[t*F + f] * att[2*F + f];
        g_vedge[t] = acc;
        return;
    }

    const float* in; const float* W; const float* a;
    float* hout; float* sout;
    if (blk < NB*OP) {
        int row = blk;
        in = x + row*F; W = Wop; a = att;
        hout = g_hop + row*F; sout = g_sop + row;
    } else {
        int row = blk - NB*OP;
        in = y + row*F; W = Wma; a = att + F;
        hout = g_h + row*F; sout = g_sma + row;
    }

    __shared__ float srow[F];
    __shared__ float sred[2];
    srow[t] = in[t];
    __syncthreads();

    float acc = 0.f;
    #pragma unroll
    for (int i = 0; i < F; i++) acc += srow[i] * W[i*F + t];
    hout[t] = acc;

    float v = warp_sum(acc * a[t]);
    if ((t & 31) == 0) sred[t >> 5] = v;
    __syncthreads();
    if (t == 0) sout[0] = sred[0] + sred[1];
}

// ---------------------------------------------------------------------------
// Main kernel: 64-thread CTA (2 warps) per (b, m) -> all 1600 CTAs resident in
// ONE wave (no wave-2 tail). Masked n's compacted into smem. Half-warp per n
// with float4 (each warp instruction covers two n's); 4 units unrolled -> 8
// z-row LDG.128 in flight per warp (MLP=8) to cover DRAM latency.
// Softmax without max-subtraction (|e| small by construction).
// ---------------------------------------------------------------------------
__global__ __launch_bounds__(64) void edge_gat_kernel(
    const float*  __restrict__ z,
    const int*    __restrict__ adj,
    const float*  __restrict__ Wedge,
    float*        __restrict__ out)
{
    const int bid = blockIdx.x;
    const int b = bid / MA;
    const int m = bid % MA;
    const int tid = threadIdx.x;
    const int w = tid >> 5;        // 0 or 1
    const int lane = tid & 31;
    const int l4 = lane & 15;      // float4 slot within half (f = 4*l4..4*l4+3)
    const int hh = lane >> 4;      // half id

    __shared__ int   s_cnt;
    __shared__ int   s_idx[OP];     // compacted masked n
    __shared__ float s_sopc[OP];    // compacted sop values
    __shared__ float4 s_pz4[2*16];
    __shared__ float4 s_ph4[2*16];
    __shared__ float s_pd[2];
    __shared__ float s_accz[F];

    if (tid == 0) s_cnt = 0;
    __syncthreads();

    // ballot-compaction; warp-uniform trip count: 448 = 7 iters for all 64 thr
    for (int i = tid; i < 448; i += 64) {
        int mk = 0;
        float sop = 0.f;
        if (i < OP) {
            mk = adj[(b*OP + i)*MA + m];     // adjT[b,m,i]
            if (mk) sop = g_sop[b*OP + i];
        }
        unsigned ball = __ballot_sync(0xffffffffu, mk != 0);
        int base = 0;
        if (lane == 0 && ball) base = atomicAdd(&s_cnt, __popc(ball));
        base = __shfl_sync(0xffffffffu, base, 0);
        if (mk) {
            int off = base + __popc(ball & ((1u << lane) - 1u));
            s_idx[off]  = i;
            s_sopc[off] = sop;
        }
    }
    const float  sma = g_sma[b*MA + m];
    const float4 ve  = ((const float4*)g_vedge)[l4];
    __syncthreads();
    const int cnt = s_cnt;
    const int U = (cnt + 1) >> 1;    // units of 2 n's

    float4 accz = make_float4(0.f, 0.f, 0.f, 0.f);
    float4 acch = make_float4(0.f, 0.f, 0.f, 0.f);
    float  denom = 0.f;   // per-half replicated; halves disjoint

    const float4* zb4 = (const float4*)z;
    const float4* hb4 = (const float4*)g_hop;

    // warp w handles units u = w + 2k; unrolled x4 -> 8 n (8 z LDG.128) in flight
    #pragma unroll 1
    for (int u0 = w; u0 < U; u0 += 8) {
        bool  ok[4]; float sop[4];
        float4 zv[4], hv[4];
        #pragma unroll
        for (int t = 0; t < 4; t++) {
            int u  = u0 + 2*t;
            int jn = 2*u + hh;
            ok[t] = (u < U) && (jn < cnt);
            int jc = ok[t] ? jn : 0;
            int n  = s_idx[jc];
            sop[t] = s_sopc[jc];
            if (ok[t]) {
                zv[t] = zb4[((b*OP + n)*MA + m)*16 + l4];
                hv[t] = hb4[(b*OP + n)*16 + l4];
            } else {
                zv[t] = make_float4(0.f,0.f,0.f,0.f);
                hv[t] = make_float4(0.f,0.f,0.f,0.f);
            }
        }
        float d[4];
        #pragma unroll
        for (int t = 0; t < 4; t++)
            d[t] = zv[t].x*ve.x + zv[t].y*ve.y + zv[t].z*ve.z + zv[t].w*ve.w;
        // 4-deep butterfly within each 16-lane half; 4 units interleaved
        #pragma unroll
        for (int o = 8; o; o >>= 1) {
            #pragma unroll
            for (int t = 0; t < 4; t++)
                d[t] += __shfl_xor_sync(0xffffffffu, d[t], o);
        }
        #pragma unroll
        for (int t = 0; t < 4; t++) {
            float e = d[t] + sop[t] + sma;
            e = fmaxf(e, 0.01f*e);                   // leaky_relu(0.01)
            float p = ok[t] ? __expf(e) : 0.f;       // no max-sub: |e| small
            denom += p;
            accz.x += p*zv[t].x; accz.y += p*zv[t].y;
            accz.z += p*zv[t].z; accz.w += p*zv[t].w;
            acch.x += p*hv[t].x; acch.y += p*hv[t].y;
            acch.z += p*hv[t].z; acch.w += p*hv[t].w;
        }
    }

    // combine halves (disjoint n-sets, same f-layout)
    accz.x += __shfl_xor_sync(0xffffffffu, accz.x, 16);
    accz.y += __shfl_xor_sync(0xffffffffu, accz.y, 16);
    accz.z += __shfl_xor_sync(0xffffffffu, accz.z, 16);
    accz.w += __shfl_xor_sync(0xffffffffu, accz.w, 16);
    acch.x += __shfl_xor_sync(0xffffffffu, acch.x, 16);
    acch.y += __shfl_xor_sync(0xffffffffu, acch.y, 16);
    acch.z += __shfl_xor_sync(0xffffffffu, acch.z, 16);
    acch.w += __shfl_xor_sync(0xffffffffu, acch.w, 16);
    denom  += __shfl_xor_sync(0xffffffffu, denom, 16);

    if (lane < 16) {
        s_pz4[w*16 + l4] = accz;
        s_ph4[w*16 + l4] = acch;
        if (lane == 0) s_pd[w] = denom;
    }
    __syncthreads();

    {
        const int f = tid;   // 64 threads = 64 features
        const float* pz = (const float*)s_pz4;
        const float* ph = (const float*)s_ph4;
        float az = pz[f] + pz[F+f];
        float ah = ph[f] + ph[F+f];
        float dn = s_pd[0] + s_pd[1];
        s_accz[f] = az;
        __syncthreads();

        float val = ah;
        #pragma unroll
        for (int kk = 0; kk < F; kk++)
            val += s_accz[kk] * Wedge[kk*F + f];
        float hbv = g_h[(b*MA + m)*F + f];
        // row_empty (dn==0): h_prime contribution zeroed -> just h
        float hp = (dn > 0.f) ? (val / dn + hbv) : hbv;
        out[(b*MA + m)*F + f] = (hp > 0.f) ? hp : expm1f(hp);   // ELU
    }
}

extern "C" void kernel_launch(void* const* d_in, const int* in_sizes, int n_in,
                              void* d_out, int out_size)
{
    const float* x    = (const float*)d_in[0];
    const float* y    = (const float*)d_in[1];
    const float* z    = (const float*)d_in[2];
    const int*   adj  = (const int*)  d_in[3];
    const float* Wop  = (const float*)d_in[4];
    const float* Wma  = (const float*)d_in[5];
    const float* We   = (const float*)d_in[6];
    const float* att  = (const float*)d_in[7];
    float* out = (float*)d_out;

    prep_kernel<<<NB*OP + NB*MA + 1, F>>>(x, y, Wop, Wma, We, att);
    edge_gat_kernel<<<NB*MA, 64>>>(z, adj, We, out);
}